// round 11
// baseline (speedup 1.0000x reference)
#include <cuda_runtime.h>
#include <cuda_bf16.h>
#include <cstdint>

// ---------------------------------------------------------------------------
// GIN, de-fused pipeline:
//   init -> fill(ELL) -> prep_w -> agg1 -> gemm1(relu) -> agg2 -> gemm2(pool)
// agg writes bf16-split rows (hi+lo, 256B/node) to global; gemm does
// m16n8k16 bf16 split-precision MMA: x@W ~= xh@Wh + xh@Wl + xl@Wh.
// NOTE: __device__ symbols are only referenced from device code (a host-side
// reference passes a shadow address -> harness violation).
// ---------------------------------------------------------------------------

#define DFEAT 64
#define NPB   64
#define XSTR  72
#define ELLW  96
#define MAX_NODES 100032

__device__ float g_h[(size_t)MAX_NODES * DFEAT];
__device__ uint2 g_xh[(size_t)MAX_NODES * 16];   // bf16 hi rows (4 bf16/uint2)
__device__ uint2 g_xl[(size_t)MAX_NODES * 16];   // bf16 lo rows
__device__ uint2 g_wh[2 * 1024];                 // W1,W2 hi, [which][n*16+kq]
__device__ uint2 g_wl[2 * 1024];
__device__ int   g_ell[(size_t)MAX_NODES * ELLW];
__device__ int   g_cnt[MAX_NODES];
__device__ int   g_is64;

__device__ __forceinline__ int ld_idx(const int* __restrict__ p, int i, int is64) {
    return is64 ? p[2 * i] : p[i];
}

#define MMA_BF16(C, a0, a1, a2, a3, b0, b1)                                   \
    asm volatile(                                                             \
        "mma.sync.aligned.m16n8k16.row.col.f32.bf16.bf16.f32 "                \
        "{%0,%1,%2,%3}, {%4,%5,%6,%7}, {%8,%9}, {%0,%1,%2,%3};"               \
        : "+f"((C)[0]), "+f"((C)[1]), "+f"((C)[2]), "+f"((C)[3])              \
        : "r"(a0), "r"(a1), "r"(a2), "r"(a3), "r"(b0), "r"(b1))

// ------------------------- init: zero cnt/out + detect ---------------------
__global__ void init_kernel(const int* __restrict__ srcw,
                            float* __restrict__ out,
                            int n_nodes, int out_n) {
    int i = blockIdx.x * blockDim.x + threadIdx.x;
    if (i < n_nodes) g_cnt[i] = 0;
    if (i < out_n) out[i] = 0.f;
    if (blockIdx.x == 0 && threadIdx.x < 32) {
        int v = srcw[2 * threadIdx.x + 1];
        unsigned ok = __ballot_sync(0xFFFFFFFFu, v == 0);
        if (threadIdx.x == 0) g_is64 = (ok == 0xFFFFFFFFu) ? 1 : 0;
    }
}

// ------------------------------- ELL fill ----------------------------------
__global__ void fill_kernel(const int* __restrict__ src,
                            const int* __restrict__ dst, int n_edges) {
    int e = blockIdx.x * blockDim.x + threadIdx.x;
    if (e >= n_edges) return;
    int is64 = g_is64;
    int d = ld_idx(dst, e, is64);
    int s = ld_idx(src, e, is64);
    int pos = atomicAdd(&g_cnt[d], 1);
    if (pos < ELLW) g_ell[(size_t)d * ELLW + pos] = s;
}

// ------------------ W split (once): fp32 [k][n] -> bf16 hi/lo [n][k] -------
__global__ void prep_w_kernel(const float* __restrict__ W1,
                              const float* __restrict__ W2) {
    int idx = blockIdx.x * blockDim.x + threadIdx.x;
    if (idx >= 2048) return;
    int which = idx >> 10;
    int r = idx & 1023;
    int n = r >> 4, kq = r & 15;
    const float* W = which ? W2 : W1;
    float w0 = __ldg(&W[(kq * 4 + 0) * DFEAT + n]);
    float w1 = __ldg(&W[(kq * 4 + 1) * DFEAT + n]);
    float w2 = __ldg(&W[(kq * 4 + 2) * DFEAT + n]);
    float w3 = __ldg(&W[(kq * 4 + 3) * DFEAT + n]);
    __nv_bfloat162 h01 = __floats2bfloat162_rn(w0, w1);
    __nv_bfloat162 h23 = __floats2bfloat162_rn(w2, w3);
    __nv_bfloat162 l01 = __floats2bfloat162_rn(w0 - __bfloat162float(h01.x),
                                               w1 - __bfloat162float(h01.y));
    __nv_bfloat162 l23 = __floats2bfloat162_rn(w2 - __bfloat162float(h23.x),
                                               w3 - __bfloat162float(h23.y));
    uint2 uh, ul;
    uh.x = *reinterpret_cast<uint32_t*>(&h01);
    uh.y = *reinterpret_cast<uint32_t*>(&h23);
    ul.x = *reinterpret_cast<uint32_t*>(&l01);
    ul.y = *reinterpret_cast<uint32_t*>(&l23);
    g_wh[idx] = uh;
    g_wl[idx] = ul;
}

// ------------------- aggregate: gather + bf16 split to global --------------
// One thread per (node, 16B chunk): 16 threads/node. 8-wide predicated
// neighbor loop; pad lanes gather self, corrected arithmetically.
// Xin == nullptr -> use g_h (device-side select; g_h never referenced on host).
__global__ __launch_bounds__(256)
void agg_kernel(const float4* __restrict__ Xin, int n_nodes) {
    int t = blockIdx.x * 256 + threadIdx.x;
    int node = t >> 4;
    if (node >= n_nodes) return;
    int c = t & 15;

    const float4* __restrict__ X4 =
        Xin ? Xin : reinterpret_cast<const float4*>(g_h);

    int deg = __ldg(&g_cnt[node]);
    deg = deg < ELLW ? deg : ELLW;
    const int* __restrict__ row = &g_ell[(size_t)node * ELLW];
    float4 self = __ldg(&X4[(size_t)node * 16 + c]);

    float4 sum = make_float4(0.f, 0.f, 0.f, 0.f);
    int G = 0;
    for (int j = 0; j < deg; j += 8) {
        int4 ja = __ldg(reinterpret_cast<const int4*>(row + j));
        int4 jb = __ldg(reinterpret_cast<const int4*>(row + j + 4));
        int rem = deg - j;
        int s0 = (rem > 0) ? ja.x : node;
        int s1 = (rem > 1) ? ja.y : node;
        int s2 = (rem > 2) ? ja.z : node;
        int s3 = (rem > 3) ? ja.w : node;
        int s4 = (rem > 4) ? jb.x : node;
        int s5 = (rem > 5) ? jb.y : node;
        int s6 = (rem > 6) ? jb.z : node;
        int s7 = (rem > 7) ? jb.w : node;
        float4 v0 = __ldg(&X4[(size_t)s0 * 16 + c]);
        float4 v1 = __ldg(&X4[(size_t)s1 * 16 + c]);
        float4 v2 = __ldg(&X4[(size_t)s2 * 16 + c]);
        float4 v3 = __ldg(&X4[(size_t)s3 * 16 + c]);
        float4 v4 = __ldg(&X4[(size_t)s4 * 16 + c]);
        float4 v5 = __ldg(&X4[(size_t)s5 * 16 + c]);
        float4 v6 = __ldg(&X4[(size_t)s6 * 16 + c]);
        float4 v7 = __ldg(&X4[(size_t)s7 * 16 + c]);
        sum.x += (v0.x + v1.x) + (v2.x + v3.x) + (v4.x + v5.x) + (v6.x + v7.x);
        sum.y += (v0.y + v1.y) + (v2.y + v3.y) + (v4.y + v5.y) + (v6.y + v7.y);
        sum.z += (v0.z + v1.z) + (v2.z + v3.z) + (v4.z + v5.z) + (v6.z + v7.z);
        sum.w += (v0.w + v1.w) + (v2.w + v3.w) + (v4.w + v5.w) + (v6.w + v7.w);
        G += 8;
    }
    float fc = (float)(1 + deg - G);
    float4 acc;
    acc.x = fmaf(fc, self.x, sum.x);
    acc.y = fmaf(fc, self.y, sum.y);
    acc.z = fmaf(fc, self.z, sum.z);
    acc.w = fmaf(fc, self.w, sum.w);

    __nv_bfloat162 h01 = __floats2bfloat162_rn(acc.x, acc.y);
    __nv_bfloat162 h23 = __floats2bfloat162_rn(acc.z, acc.w);
    __nv_bfloat162 q01 = __floats2bfloat162_rn(acc.x - __bfloat162float(h01.x),
                                               acc.y - __bfloat162float(h01.y));
    __nv_bfloat162 q23 = __floats2bfloat162_rn(acc.z - __bfloat162float(h23.x),
                                               acc.w - __bfloat162float(h23.y));
    uint2 uh, ul;
    uh.x = *reinterpret_cast<uint32_t*>(&h01);
    uh.y = *reinterpret_cast<uint32_t*>(&h23);
    ul.x = *reinterpret_cast<uint32_t*>(&q01);
    ul.y = *reinterpret_cast<uint32_t*>(&q23);
    g_xh[(size_t)node * 16 + c] = uh;
    g_xl[(size_t)node * 16 + c] = ul;
}

// --------------------------- shared GEMM pieces ----------------------------
__device__ __forceinline__ void stage_w(__nv_bfloat16* __restrict__ wh,
                                        __nv_bfloat16* __restrict__ wl,
                                        int which, int tid) {
    const uint2* gh = g_wh + which * 1024;
    const uint2* gl = g_wl + which * 1024;
    for (int idx = tid; idx < 1024; idx += 128) {
        int n = idx >> 4, kq = idx & 15;
        *reinterpret_cast<uint2*>(&wh[n * XSTR + kq * 4]) = __ldg(&gh[idx]);
        *reinterpret_cast<uint2*>(&wl[n * XSTR + kq * 4]) = __ldg(&gl[idx]);
    }
}

__device__ __forceinline__ void stage_x(__nv_bfloat16* __restrict__ xh,
                                        __nv_bfloat16* __restrict__ xl,
                                        int n0, int n_nodes, int tid) {
    uint2 z; z.x = 0u; z.y = 0u;
    for (int idx = tid; idx < NPB * 16; idx += 128) {
        int slot = idx >> 4, cq = idx & 15;
        int node = n0 + slot;
        uint2 vh = z, vl = z;
        if (node < n_nodes) {
            vh = __ldg(&g_xh[(size_t)node * 16 + cq]);
            vl = __ldg(&g_xl[(size_t)node * 16 + cq]);
        }
        *reinterpret_cast<uint2*>(&xh[slot * XSTR + cq * 4]) = vh;
        *reinterpret_cast<uint2*>(&xl[slot * XSTR + cq * 4]) = vl;
    }
}

__device__ __forceinline__ void mma_phase(const __nv_bfloat16* __restrict__ xh,
                                          const __nv_bfloat16* __restrict__ xl,
                                          const __nv_bfloat16* __restrict__ wh,
                                          const __nv_bfloat16* __restrict__ wl,
                                          int warp, int lane, float C[8][4]) {
    int r = lane >> 2;
    int cq = (lane & 3) * 2;
#pragma unroll
    for (int nt = 0; nt < 8; nt++) {
        C[nt][0] = 0.f; C[nt][1] = 0.f; C[nt][2] = 0.f; C[nt][3] = 0.f;
    }
    int row0 = warp * 16 + r;
#pragma unroll
    for (int kt = 0; kt < 4; kt++) {
        int kb = kt * 16 + cq;
        uint32_t ah0 = *reinterpret_cast<const uint32_t*>(&xh[row0 * XSTR + kb]);
        uint32_t ah1 = *reinterpret_cast<const uint32_t*>(&xh[(row0 + 8) * XSTR + kb]);
        uint32_t ah2 = *reinterpret_cast<const uint32_t*>(&xh[row0 * XSTR + kb + 8]);
        uint32_t ah3 = *reinterpret_cast<const uint32_t*>(&xh[(row0 + 8) * XSTR + kb + 8]);
        uint32_t al0 = *reinterpret_cast<const uint32_t*>(&xl[row0 * XSTR + kb]);
        uint32_t al1 = *reinterpret_cast<const uint32_t*>(&xl[(row0 + 8) * XSTR + kb]);
        uint32_t al2 = *reinterpret_cast<const uint32_t*>(&xl[row0 * XSTR + kb + 8]);
        uint32_t al3 = *reinterpret_cast<const uint32_t*>(&xl[(row0 + 8) * XSTR + kb + 8]);
#pragma unroll
        for (int nt = 0; nt < 8; nt++) {
            int nrow = nt * 8 + r;
            uint32_t bh0 = *reinterpret_cast<const uint32_t*>(&wh[nrow * XSTR + kb]);
            uint32_t bh1 = *reinterpret_cast<const uint32_t*>(&wh[nrow * XSTR + kb + 8]);
            uint32_t bl0 = *reinterpret_cast<const uint32_t*>(&wl[nrow * XSTR + kb]);
            uint32_t bl1 = *reinterpret_cast<const uint32_t*>(&wl[nrow * XSTR + kb + 8]);
            MMA_BF16(C[nt], ah0, ah1, ah2, ah3, bh0, bh1);
            MMA_BF16(C[nt], ah0, ah1, ah2, ah3, bl0, bl1);
            MMA_BF16(C[nt], al0, al1, al2, al3, bh0, bh1);
        }
    }
}

// -------------------------- gemm1: x@W1 + b1, relu -------------------------
__global__ __launch_bounds__(128)
void gemm_relu_kernel(const float* __restrict__ B, int n_nodes) {
    __shared__ __align__(16) __nv_bfloat16 xh[NPB * XSTR];
    __shared__ __align__(16) __nv_bfloat16 xl[NPB * XSTR];
    __shared__ __align__(16) __nv_bfloat16 wh[DFEAT * XSTR];
    __shared__ __align__(16) __nv_bfloat16 wl[DFEAT * XSTR];

    int tid = threadIdx.x;
    int n0 = blockIdx.x * NPB;
    stage_w(wh, wl, 0, tid);
    stage_x(xh, xl, n0, n_nodes, tid);
    __syncthreads();

    int warp = tid >> 5, lane = tid & 31;
    float C[8][4];
    mma_phase(xh, xl, wh, wl, warp, lane, C);

    int r = lane >> 2;
    int cq = (lane & 3) * 2;
    int node0 = n0 + warp * 16 + r;
    int node1 = node0 + 8;
#pragma unroll
    for (int nt = 0; nt < 8; nt++) {
        int col = nt * 8 + cq;
        float2 bv = __ldg(reinterpret_cast<const float2*>(B + col));
        if (node0 < n_nodes) {
            float2 y;
            y.x = fmaxf(C[nt][0] + bv.x, 0.f);
            y.y = fmaxf(C[nt][1] + bv.y, 0.f);
            *reinterpret_cast<float2*>(&g_h[(size_t)node0 * DFEAT + col]) = y;
        }
        if (node1 < n_nodes) {
            float2 y;
            y.x = fmaxf(C[nt][2] + bv.x, 0.f);
            y.y = fmaxf(C[nt][3] + bv.y, 0.f);
            *reinterpret_cast<float2*>(&g_h[(size_t)node1 * DFEAT + col]) = y;
        }
    }
}

// ----------------------- gemm2: x@W2 + b2, then pool -----------------------
__global__ __launch_bounds__(128)
void gemm_pool_kernel(const float* __restrict__ B,
                      const int* __restrict__ gid,
                      float* __restrict__ out, int n_nodes) {
    __shared__ __align__(16) __nv_bfloat16 xh[NPB * XSTR];
    __shared__ __align__(16) __nv_bfloat16 xl[NPB * XSTR];
    __shared__ __align__(16) __nv_bfloat16 wh[DFEAT * XSTR];
    __shared__ __align__(16) __nv_bfloat16 wl[DFEAT * XSTR];

    int tid = threadIdx.x;
    int n0 = blockIdx.x * NPB;
    stage_w(wh, wl, 1, tid);
    stage_x(xh, xl, n0, n_nodes, tid);
    __syncthreads();

    int warp = tid >> 5, lane = tid & 31;
    float C[8][4];
    mma_phase(xh, xl, wh, wl, warp, lane, C);
    __syncthreads();   // xh/xl reads done before reuse as fp32 staging

    float* xsf = reinterpret_cast<float*>(xh);   // 16 KB fits in xh+xl (18 KB)
    {
        int r = lane >> 2;
        int cq = (lane & 3) * 2;
        int row0 = warp * 16 + r;
#pragma unroll
        for (int nt = 0; nt < 8; nt++) {
            int col = nt * 8 + cq;
            float2 bv = __ldg(reinterpret_cast<const float2*>(B + col));
            float2 y0, y1;
            y0.x = C[nt][0] + bv.x; y0.y = C[nt][1] + bv.y;
            y1.x = C[nt][2] + bv.x; y1.y = C[nt][3] + bv.y;
            *reinterpret_cast<float2*>(&xsf[row0 * DFEAT + col]) = y0;
            *reinterpret_cast<float2*>(&xsf[(row0 + 8) * DFEAT + col]) = y1;
        }
    }
    __syncthreads();

    // graph_id sorted: 128 threads = 2 node-halves x 64 cols.
    {
        int col = tid & 63;
        int half = tid >> 6;
        int i0 = half * (NPB / 2);
        int i1 = i0 + (NPB / 2);
        int is64 = g_is64;
        float a = 0.f;
        int cur = -1;
        for (int i = i0; i < i1; i++) {
            int node = n0 + i;
            if (node >= n_nodes) break;
            int g = ld_idx(gid, node, is64);
            if (g != cur) {
                if (cur >= 0) atomicAdd(&out[(size_t)cur * DFEAT + col], a);
                cur = g;
                a = 0.f;
            }
            a += xsf[i * DFEAT + col];
        }
        if (cur >= 0) atomicAdd(&out[(size_t)cur * DFEAT + col], a);
    }
}

// ------------------------------- launcher ----------------------------------
extern "C" void kernel_launch(void* const* d_in, const int* in_sizes, int n_in,
                              void* d_out, int out_size) {
    const float* feats = (const float*)d_in[0];
    const int*   src   = (const int*)d_in[1];
    const int*   dst   = (const int*)d_in[2];
    const int*   gid   = (const int*)d_in[3];
    const float* W1    = (const float*)d_in[4];
    const float* b1    = (const float*)d_in[5];
    const float* W2    = (const float*)d_in[6];
    const float* b2    = (const float*)d_in[7];
    float* out = (float*)d_out;

    int n_nodes = in_sizes[0] / DFEAT;
    int n_edges = in_sizes[1];

    int igrid = ((n_nodes > out_size ? n_nodes : out_size) + 255) / 256;
    int egrid = (n_edges + 255) / 256;
    int agrid = (n_nodes * 16 + 255) / 256;
    int ggrid = (n_nodes + NPB - 1) / NPB;

    init_kernel<<<igrid, 256>>>(src, out, n_nodes, out_size);
    fill_kernel<<<egrid, 256>>>(src, dst, n_edges);
    prep_w_kernel<<<8, 256>>>(W1, W2);

    agg_kernel<<<agrid, 256>>>(reinterpret_cast<const float4*>(feats), n_nodes);
    gemm_relu_kernel<<<ggrid, 128>>>(b1, n_nodes);

    agg_kernel<<<agrid, 256>>>(nullptr, n_nodes);   // X = g_h (device select)
    gemm_pool_kernel<<<ggrid, 128>>>(b2, gid, out, n_nodes);
}

// round 12
// speedup vs baseline: 1.3032x; 1.3032x over previous
#include <cuda_runtime.h>
#include <cuda_fp16.h>
#include <cstdint>

// ---------------------------------------------------------------------------
// GIN, fused layers with fp16 gather operands (halves L2 gather traffic):
//   prep_x: feats fp32 -> fp16 rows (128B)
//   fused1: gather fp16 + split-precision fp16 MMA -> h written as fp16
//   fused2: gather fp16 h + MMA + bias + sorted-gid pooling
// GEMM: x@W ~= xh@Wh + xh@Wl + xl@Wh (fp16 operands, fp32 accum).
// ---------------------------------------------------------------------------

#define DFEAT 64
#define NPB   64
#define LTHR  256
#define NGRP  16       // 16-thread gather groups -> 4 slots/group
#define XSTR  72       // fp16 row stride in smem (144B)
#define ELLW  96
#define MAX_NODES 100032

__device__ uint2 g_x16[(size_t)MAX_NODES * 16];   // fp16 feats rows
__device__ uint2 g_h16[(size_t)MAX_NODES * 16];   // fp16 h rows
__device__ uint2 g_wh[2 * 1024];                  // W hi fp16 [which][n*16+kq]
__device__ uint2 g_wl[2 * 1024];                  // W lo fp16
__device__ int   g_ell[(size_t)MAX_NODES * ELLW];
__device__ int   g_cnt[MAX_NODES];
__device__ int   g_is64;

__device__ __forceinline__ int ld_idx(const int* __restrict__ p, int i, int is64) {
    return is64 ? p[2 * i] : p[i];
}

#define MMA_F16(C, a0, a1, a2, a3, b0, b1)                                    \
    asm volatile(                                                             \
        "mma.sync.aligned.m16n8k16.row.col.f32.f16.f16.f32 "                  \
        "{%0,%1,%2,%3}, {%4,%5,%6,%7}, {%8,%9}, {%0,%1,%2,%3};"               \
        : "+f"((C)[0]), "+f"((C)[1]), "+f"((C)[2]), "+f"((C)[3])              \
        : "r"(a0), "r"(a1), "r"(a2), "r"(a3), "r"(b0), "r"(b1))

__device__ __forceinline__ float4 h4f(uint2 u) {
    __half2 a = *reinterpret_cast<__half2*>(&u.x);
    __half2 b = *reinterpret_cast<__half2*>(&u.y);
    float2 fa = __half22float2(a);
    float2 fb = __half22float2(b);
    return make_float4(fa.x, fa.y, fb.x, fb.y);
}

// ------------------------- init: zero cnt/out + detect ---------------------
__global__ void init_kernel(const int* __restrict__ srcw,
                            float* __restrict__ out,
                            int n_nodes, int out_n) {
    int i = blockIdx.x * blockDim.x + threadIdx.x;
    if (i < n_nodes) g_cnt[i] = 0;
    if (i < out_n) out[i] = 0.f;
    if (blockIdx.x == 0 && threadIdx.x < 32) {
        int v = srcw[2 * threadIdx.x + 1];
        unsigned ok = __ballot_sync(0xFFFFFFFFu, v == 0);
        if (threadIdx.x == 0) g_is64 = (ok == 0xFFFFFFFFu) ? 1 : 0;
    }
}

// ------------------------------- ELL fill ----------------------------------
__global__ void fill_kernel(const int* __restrict__ src,
                            const int* __restrict__ dst, int n_edges) {
    int e = blockIdx.x * blockDim.x + threadIdx.x;
    if (e >= n_edges) return;
    int is64 = g_is64;
    int d = ld_idx(dst, e, is64);
    int s = ld_idx(src, e, is64);
    int pos = atomicAdd(&g_cnt[d], 1);
    if (pos < ELLW) g_ell[(size_t)d * ELLW + pos] = s;
}

// -------------- W split (once): fp32 [k][n] -> fp16 hi/lo [n][k] -----------
__global__ void prep_w_kernel(const float* __restrict__ W1,
                              const float* __restrict__ W2) {
    int idx = blockIdx.x * blockDim.x + threadIdx.x;
    if (idx >= 2048) return;
    int which = idx >> 10;
    int r = idx & 1023;
    int n = r >> 4, kq = r & 15;
    const float* W = which ? W2 : W1;
    float w0 = __ldg(&W[(kq * 4 + 0) * DFEAT + n]);
    float w1 = __ldg(&W[(kq * 4 + 1) * DFEAT + n]);
    float w2 = __ldg(&W[(kq * 4 + 2) * DFEAT + n]);
    float w3 = __ldg(&W[(kq * 4 + 3) * DFEAT + n]);
    __half2 h01 = __floats2half2_rn(w0, w1);
    __half2 h23 = __floats2half2_rn(w2, w3);
    __half2 l01 = __floats2half2_rn(w0 - __low2float(h01), w1 - __high2float(h01));
    __half2 l23 = __floats2half2_rn(w2 - __low2float(h23), w3 - __high2float(h23));
    uint2 uh, ul;
    uh.x = *reinterpret_cast<uint32_t*>(&h01);
    uh.y = *reinterpret_cast<uint32_t*>(&h23);
    ul.x = *reinterpret_cast<uint32_t*>(&l01);
    ul.y = *reinterpret_cast<uint32_t*>(&l23);
    g_wh[idx] = uh;
    g_wl[idx] = ul;
}

// -------------------- feats fp32 -> fp16 rows (once) -----------------------
__global__ void prep_x_kernel(const float4* __restrict__ X4, int n4) {
    int t = blockIdx.x * blockDim.x + threadIdx.x;
    if (t >= n4) return;
    float4 v = __ldg(&X4[t]);
    __half2 a = __floats2half2_rn(v.x, v.y);
    __half2 b = __floats2half2_rn(v.z, v.w);
    uint2 u;
    u.x = *reinterpret_cast<uint32_t*>(&a);
    u.y = *reinterpret_cast<uint32_t*>(&b);
    g_x16[t] = u;
}

// --------------- aggregate: fp16 gather -> fp16-split smem rows ------------
// 16 groups of 16 threads; group handles 4 slots. Thread owns 4 fp16 (8B) of
// the node's 128B row; 8-wide predicated neighbor loop (pad lanes gather
// self, corrected arithmetically); fp32 accumulate; hi/lo fp16 split out.
__device__ __forceinline__ void aggregate_phase(const uint2* __restrict__ X16,
                                                __half* __restrict__ xh,
                                                __half* __restrict__ xl,
                                                int n0, int n_nodes, int tid) {
    int gidx = tid >> 4;
    int c = tid & 15;
#pragma unroll
    for (int k = 0; k < NPB / NGRP; k++) {
        int slot = gidx + k * NGRP;
        int node = n0 + slot;
        float4 acc = make_float4(0.f, 0.f, 0.f, 0.f);
        if (node < n_nodes) {
            int deg = __ldg(&g_cnt[node]);
            deg = deg < ELLW ? deg : ELLW;
            const int* __restrict__ row = &g_ell[(size_t)node * ELLW];
            float4 self = h4f(__ldg(&X16[(size_t)node * 16 + c]));
            float4 sum = make_float4(0.f, 0.f, 0.f, 0.f);
            int G = 0;
            for (int j = 0; j < deg; j += 8) {
                int4 ja = __ldg(reinterpret_cast<const int4*>(row + j));
                int4 jb = __ldg(reinterpret_cast<const int4*>(row + j + 4));
                int rem = deg - j;
                int s0 = (rem > 0) ? ja.x : node;
                int s1 = (rem > 1) ? ja.y : node;
                int s2 = (rem > 2) ? ja.z : node;
                int s3 = (rem > 3) ? ja.w : node;
                int s4 = (rem > 4) ? jb.x : node;
                int s5 = (rem > 5) ? jb.y : node;
                int s6 = (rem > 6) ? jb.z : node;
                int s7 = (rem > 7) ? jb.w : node;
                float4 v0 = h4f(__ldg(&X16[(size_t)s0 * 16 + c]));
                float4 v1 = h4f(__ldg(&X16[(size_t)s1 * 16 + c]));
                float4 v2 = h4f(__ldg(&X16[(size_t)s2 * 16 + c]));
                float4 v3 = h4f(__ldg(&X16[(size_t)s3 * 16 + c]));
                float4 v4 = h4f(__ldg(&X16[(size_t)s4 * 16 + c]));
                float4 v5 = h4f(__ldg(&X16[(size_t)s5 * 16 + c]));
                float4 v6 = h4f(__ldg(&X16[(size_t)s6 * 16 + c]));
                float4 v7 = h4f(__ldg(&X16[(size_t)s7 * 16 + c]));
                sum.x += (v0.x + v1.x) + (v2.x + v3.x) + (v4.x + v5.x) + (v6.x + v7.x);
                sum.y += (v0.y + v1.y) + (v2.y + v3.y) + (v4.y + v5.y) + (v6.y + v7.y);
                sum.z += (v0.z + v1.z) + (v2.z + v3.z) + (v4.z + v5.z) + (v6.z + v7.z);
                sum.w += (v0.w + v1.w) + (v2.w + v3.w) + (v4.w + v5.w) + (v6.w + v7.w);
                G += 8;
            }
            float fc = (float)(1 + deg - G);
            acc.x = fmaf(fc, self.x, sum.x);
            acc.y = fmaf(fc, self.y, sum.y);
            acc.z = fmaf(fc, self.z, sum.z);
            acc.w = fmaf(fc, self.w, sum.w);
        }
        __half2 h01 = __floats2half2_rn(acc.x, acc.y);
        __half2 h23 = __floats2half2_rn(acc.z, acc.w);
        __half2 q01 = __floats2half2_rn(acc.x - __low2float(h01),
                                        acc.y - __high2float(h01));
        __half2 q23 = __floats2half2_rn(acc.z - __low2float(h23),
                                        acc.w - __high2float(h23));
        uint32_t* ph = reinterpret_cast<uint32_t*>(&xh[slot * XSTR + 4 * c]);
        uint32_t* pl = reinterpret_cast<uint32_t*>(&xl[slot * XSTR + 4 * c]);
        ph[0] = *reinterpret_cast<uint32_t*>(&h01);
        ph[1] = *reinterpret_cast<uint32_t*>(&h23);
        pl[0] = *reinterpret_cast<uint32_t*>(&q01);
        pl[1] = *reinterpret_cast<uint32_t*>(&q23);
    }
}

// ------------------- stage W split from global into smem -------------------
__device__ __forceinline__ void stage_w(__half* __restrict__ wh,
                                        __half* __restrict__ wl,
                                        int which, int tid) {
    const uint2* gh = g_wh + which * 1024;
    const uint2* gl = g_wl + which * 1024;
    for (int idx = tid; idx < 1024; idx += LTHR) {
        int n = idx >> 4, kq = idx & 15;
        *reinterpret_cast<uint2*>(&wh[n * XSTR + kq * 4]) = __ldg(&gh[idx]);
        *reinterpret_cast<uint2*>(&wl[n * XSTR + kq * 4]) = __ldg(&gl[idx]);
    }
}

// ------ MMA: 8 warps; warp = (wrow 0-3)x16 rows, (whalf 0-1)x32 cols -------
__device__ __forceinline__ void mma_phase(const __half* __restrict__ xh,
                                          const __half* __restrict__ xl,
                                          const __half* __restrict__ wh,
                                          const __half* __restrict__ wl,
                                          int wrow, int whalf, int lane,
                                          float C[4][4]) {
    int r = lane >> 2;
    int cq = (lane & 3) * 2;
#pragma unroll
    for (int nt = 0; nt < 4; nt++) {
        C[nt][0] = 0.f; C[nt][1] = 0.f; C[nt][2] = 0.f; C[nt][3] = 0.f;
    }
    int row0 = wrow * 16 + r;
#pragma unroll
    for (int kt = 0; kt < 4; kt++) {
        int kb = kt * 16 + cq;
        uint32_t ah0 = *reinterpret_cast<const uint32_t*>(&xh[row0 * XSTR + kb]);
        uint32_t ah1 = *reinterpret_cast<const uint32_t*>(&xh[(row0 + 8) * XSTR + kb]);
        uint32_t ah2 = *reinterpret_cast<const uint32_t*>(&xh[row0 * XSTR + kb + 8]);
        uint32_t ah3 = *reinterpret_cast<const uint32_t*>(&xh[(row0 + 8) * XSTR + kb + 8]);
        uint32_t al0 = *reinterpret_cast<const uint32_t*>(&xl[row0 * XSTR + kb]);
        uint32_t al1 = *reinterpret_cast<const uint32_t*>(&xl[(row0 + 8) * XSTR + kb]);
        uint32_t al2 = *reinterpret_cast<const uint32_t*>(&xl[row0 * XSTR + kb + 8]);
        uint32_t al3 = *reinterpret_cast<const uint32_t*>(&xl[(row0 + 8) * XSTR + kb + 8]);
#pragma unroll
        for (int nt = 0; nt < 4; nt++) {
            int nrow = (whalf * 4 + nt) * 8 + r;
            uint32_t bh0 = *reinterpret_cast<const uint32_t*>(&wh[nrow * XSTR + kb]);
            uint32_t bh1 = *reinterpret_cast<const uint32_t*>(&wh[nrow * XSTR + kb + 8]);
            uint32_t bl0 = *reinterpret_cast<const uint32_t*>(&wl[nrow * XSTR + kb]);
            uint32_t bl1 = *reinterpret_cast<const uint32_t*>(&wl[nrow * XSTR + kb + 8]);
            MMA_F16(C[nt], ah0, ah1, ah2, ah3, bh0, bh1);
            MMA_F16(C[nt], ah0, ah1, ah2, ah3, bl0, bl1);
            MMA_F16(C[nt], al0, al1, al2, al3, bh0, bh1);
        }
    }
}

// ----------------- fused layer 1: agg + GEMM + relu -> fp16 h --------------
__global__ __launch_bounds__(LTHR, 5)
void fused_layer1_kernel(const float* __restrict__ B, int n_nodes) {
    __shared__ __align__(16) __half xsp[2 * NPB * XSTR];    // 18 KB
    __shared__ __align__(16) __half wsp[2 * DFEAT * XSTR];  // 18 KB
    __half* xh = xsp;
    __half* xl = xsp + NPB * XSTR;
    __half* wh = wsp;
    __half* wl = wsp + DFEAT * XSTR;

    int tid = threadIdx.x;
    int n0 = blockIdx.x * NPB;
    stage_w(wh, wl, 0, tid);
    aggregate_phase(g_x16, xh, xl, n0, n_nodes, tid);
    __syncthreads();

    int warp = tid >> 5, lane = tid & 31;
    int wrow = warp & 3, whalf = warp >> 2;
    float C[4][4];
    mma_phase(xh, xl, wh, wl, wrow, whalf, lane, C);

    int r = lane >> 2;
    int cq = (lane & 3) * 2;
    int node0 = n0 + wrow * 16 + r;
    int node1 = node0 + 8;
    uint32_t* H = reinterpret_cast<uint32_t*>(g_h16);
#pragma unroll
    for (int nt = 0; nt < 4; nt++) {
        int col = (whalf * 4 + nt) * 8 + cq;
        float2 bv = __ldg(reinterpret_cast<const float2*>(B + col));
        if (node0 < n_nodes) {
            __half2 y = __floats2half2_rn(fmaxf(C[nt][0] + bv.x, 0.f),
                                          fmaxf(C[nt][1] + bv.y, 0.f));
            H[(size_t)node0 * 32 + (col >> 1)] = *reinterpret_cast<uint32_t*>(&y);
        }
        if (node1 < n_nodes) {
            __half2 y = __floats2half2_rn(fmaxf(C[nt][2] + bv.x, 0.f),
                                          fmaxf(C[nt][3] + bv.y, 0.f));
            H[(size_t)node1 * 32 + (col >> 1)] = *reinterpret_cast<uint32_t*>(&y);
        }
    }
}

// ------------------ fused layer 2: agg + GEMM + pooling --------------------
__global__ __launch_bounds__(LTHR, 5)
void fused_layer2_kernel(const float* __restrict__ B,
                         const int* __restrict__ gid,
                         float* __restrict__ out, int n_nodes) {
    __shared__ __align__(16) __half xsp[2 * NPB * XSTR];
    __shared__ __align__(16) __half wsp[2 * DFEAT * XSTR];
    __half* xh = xsp;
    __half* xl = xsp + NPB * XSTR;
    __half* wh = wsp;
    __half* wl = wsp + DFEAT * XSTR;

    int tid = threadIdx.x;
    int n0 = blockIdx.x * NPB;
    stage_w(wh, wl, 1, tid);
    aggregate_phase(g_h16, xh, xl, n0, n_nodes, tid);
    __syncthreads();

    int warp = tid >> 5, lane = tid & 31;
    int wrow = warp & 3, whalf = warp >> 2;
    float C[4][4];
    mma_phase(xh, xl, wh, wl, wrow, whalf, lane, C);
    __syncthreads();   // xsp reads done before reuse as fp32 staging

    float* xsf = reinterpret_cast<float*>(xsp);   // 16 KB fits in 18 KB
    {
        int r = lane >> 2;
        int cq = (lane & 3) * 2;
        int row0 = wrow * 16 + r;
#pragma unroll
        for (int nt = 0; nt < 4; nt++) {
            int col = (whalf * 4 + nt) * 8 + cq;
            float2 bv = __ldg(reinterpret_cast<const float2*>(B + col));
            float2 y0, y1;
            y0.x = C[nt][0] + bv.x; y0.y = C[nt][1] + bv.y;
            y1.x = C[nt][2] + bv.x; y1.y = C[nt][3] + bv.y;
            *reinterpret_cast<float2*>(&xsf[row0 * DFEAT + col]) = y0;
            *reinterpret_cast<float2*>(&xsf[(row0 + 8) * DFEAT + col]) = y1;
        }
    }
    __syncthreads();

    // graph_id sorted: 128 threads = 2 node-halves x 64 cols.
    if (tid < 2 * DFEAT) {
        int col = tid & 63;
        int half = tid >> 6;
        int i0 = half * (NPB / 2);
        int i1 = i0 + (NPB / 2);
        int is64 = g_is64;
        float a = 0.f;
        int cur = -1;
        for (int i = i0; i < i1; i++) {
            int node = n0 + i;
            if (node >= n_nodes) break;
            int g = ld_idx(gid, node, is64);
            if (g != cur) {
                if (cur >= 0) atomicAdd(&out[(size_t)cur * DFEAT + col], a);
                cur = g;
                a = 0.f;
            }
            a += xsf[i * DFEAT + col];
        }
        if (cur >= 0) atomicAdd(&out[(size_t)cur * DFEAT + col], a);
    }
}

// ------------------------------- launcher ----------------------------------
extern "C" void kernel_launch(void* const* d_in, const int* in_sizes, int n_in,
                              void* d_out, int out_size) {
    const float* feats = (const float*)d_in[0];
    const int*   src   = (const int*)d_in[1];
    const int*   dst   = (const int*)d_in[2];
    const int*   gid   = (const int*)d_in[3];
    const float* W1    = (const float*)d_in[4];
    const float* b1    = (const float*)d_in[5];
    const float* W2    = (const float*)d_in[6];
    const float* b2    = (const float*)d_in[7];
    float* out = (float*)d_out;

    int n_nodes = in_sizes[0] / DFEAT;
    int n_edges = in_sizes[1];
    int n4 = n_nodes * 16;

    int igrid = ((n_nodes > out_size ? n_nodes : out_size) + 255) / 256;
    int egrid = (n_edges + 255) / 256;
    int pgrid = (n4 + 255) / 256;
    int lgrid = (n_nodes + NPB - 1) / NPB;

    init_kernel<<<igrid, 256>>>(src, out, n_nodes, out_size);
    fill_kernel<<<egrid, 256>>>(src, dst, n_edges);
    prep_w_kernel<<<8, 256>>>(W1, W2);
    prep_x_kernel<<<pgrid, 256>>>(reinterpret_cast<const float4*>(feats), n4);

    fused_layer1_kernel<<<lgrid, LTHR>>>(b1, n_nodes);
    fused_layer2_kernel<<<lgrid, LTHR>>>(b2, gid, out, n_nodes);
}

// round 13
// speedup vs baseline: 1.4686x; 1.1270x over previous
#include <cuda_runtime.h>
#include <cuda_fp16.h>
#include <cstdint>

// ---------------------------------------------------------------------------
// GIN, fused layers with fp16 gather operands:
//   setup: zero cnt/out + int64-detect + W split + feats->fp16 (ONE kernel)
//   fill:  ELL adjacency
//   fused1: gather fp16 (uint4 chunks) + split fp16 MMA -> h as fp16
//   fused2: gather fp16 h + MMA + bias + sorted-gid pooling
// GEMM: x@W ~= xh@Wh + xh@Wl + xl@Wh (fp16 operands, fp32 accum).
// ---------------------------------------------------------------------------

#define DFEAT 64
#define NPB   64
#define LTHR  256
#define GTH   8        // threads per node in gather (16B chunk each)
#define XSTR  72       // fp16 row stride in smem (144B)
#define ELLW  96
#define MAX_NODES 100032

__device__ uint4 g_x16[(size_t)MAX_NODES * 8];   // fp16 feats rows (128B)
__device__ uint4 g_h16[(size_t)MAX_NODES * 8];   // fp16 h rows
__device__ uint2 g_wh[2 * 1024];                 // W hi fp16 [which][n*16+kq]
__device__ uint2 g_wl[2 * 1024];                 // W lo fp16
__device__ int   g_ell[(size_t)MAX_NODES * ELLW];
__device__ int   g_cnt[MAX_NODES];
__device__ int   g_is64;

__device__ __forceinline__ int ld_idx(const int* __restrict__ p, int i, int is64) {
    return is64 ? p[2 * i] : p[i];
}

#define MMA_F16(C, a0, a1, a2, a3, b0, b1)                                    \
    asm volatile(                                                             \
        "mma.sync.aligned.m16n8k16.row.col.f32.f16.f16.f32 "                  \
        "{%0,%1,%2,%3}, {%4,%5,%6,%7}, {%8,%9}, {%0,%1,%2,%3};"               \
        : "+f"((C)[0]), "+f"((C)[1]), "+f"((C)[2]), "+f"((C)[3])              \
        : "r"(a0), "r"(a1), "r"(a2), "r"(a3), "r"(b0), "r"(b1))

// uint4 (8 fp16) -> two float4
__device__ __forceinline__ void cvt8(uint4 u, float4& A, float4& B) {
    __half2 h0 = *reinterpret_cast<__half2*>(&u.x);
    __half2 h1 = *reinterpret_cast<__half2*>(&u.y);
    __half2 h2 = *reinterpret_cast<__half2*>(&u.z);
    __half2 h3 = *reinterpret_cast<__half2*>(&u.w);
    float2 f0 = __half22float2(h0);
    float2 f1 = __half22float2(h1);
    float2 f2 = __half22float2(h2);
    float2 f3 = __half22float2(h3);
    A = make_float4(f0.x, f0.y, f1.x, f1.y);
    B = make_float4(f2.x, f2.y, f3.x, f3.y);
}

// ---------------- setup: zero + detect + W split + feats->fp16 -------------
__global__ void setup_kernel(const float4* __restrict__ X4,
                             const float* __restrict__ W1,
                             const float* __restrict__ W2,
                             const int* __restrict__ srcw,
                             float* __restrict__ out,
                             int n_nodes, int out_n, int n8) {
    int i = blockIdx.x * blockDim.x + threadIdx.x;
    if (i < n_nodes) g_cnt[i] = 0;
    if (i < out_n) out[i] = 0.f;
    if (blockIdx.x == 0 && threadIdx.x < 32) {
        int v = srcw[2 * threadIdx.x + 1];
        unsigned ok = __ballot_sync(0xFFFFFFFFu, v == 0);
        if (threadIdx.x == 0) g_is64 = (ok == 0xFFFFFFFFu) ? 1 : 0;
    }
    if (i < 2048) {   // W split: fp32 [k][n] -> fp16 hi/lo [n][k]
        int which = i >> 10;
        int r = i & 1023;
        int n = r >> 4, kq = r & 15;
        const float* W = which ? W2 : W1;
        float w0 = __ldg(&W[(kq * 4 + 0) * DFEAT + n]);
        float w1 = __ldg(&W[(kq * 4 + 1) * DFEAT + n]);
        float w2 = __ldg(&W[(kq * 4 + 2) * DFEAT + n]);
        float w3 = __ldg(&W[(kq * 4 + 3) * DFEAT + n]);
        __half2 h01 = __floats2half2_rn(w0, w1);
        __half2 h23 = __floats2half2_rn(w2, w3);
        __half2 l01 = __floats2half2_rn(w0 - __low2float(h01), w1 - __high2float(h01));
        __half2 l23 = __floats2half2_rn(w2 - __low2float(h23), w3 - __high2float(h23));
        uint2 uh, ul;
        uh.x = *reinterpret_cast<uint32_t*>(&h01);
        uh.y = *reinterpret_cast<uint32_t*>(&h23);
        ul.x = *reinterpret_cast<uint32_t*>(&l01);
        ul.y = *reinterpret_cast<uint32_t*>(&l23);
        g_wh[i] = uh;
        g_wl[i] = ul;
    }
    if (i < n8) {     // feats fp32 -> fp16 (8 values per thread)
        float4 a = __ldg(&X4[2 * i]);
        float4 b = __ldg(&X4[2 * i + 1]);
        __half2 h0 = __floats2half2_rn(a.x, a.y);
        __half2 h1 = __floats2half2_rn(a.z, a.w);
        __half2 h2 = __floats2half2_rn(b.x, b.y);
        __half2 h3 = __floats2half2_rn(b.z, b.w);
        uint4 u;
        u.x = *reinterpret_cast<uint32_t*>(&h0);
        u.y = *reinterpret_cast<uint32_t*>(&h1);
        u.z = *reinterpret_cast<uint32_t*>(&h2);
        u.w = *reinterpret_cast<uint32_t*>(&h3);
        g_x16[i] = u;
    }
}

// ------------------------------- ELL fill ----------------------------------
__global__ void fill_kernel(const int* __restrict__ src,
                            const int* __restrict__ dst, int n_edges) {
    int e = blockIdx.x * blockDim.x + threadIdx.x;
    if (e >= n_edges) return;
    int is64 = g_is64;
    int d = ld_idx(dst, e, is64);
    int s = ld_idx(src, e, is64);
    int pos = atomicAdd(&g_cnt[d], 1);
    if (pos < ELLW) g_ell[(size_t)d * ELLW + pos] = s;
}

// -------------- aggregate: fp16 uint4 gather -> fp16-split smem ------------
// 32 groups of 8 threads; group handles 2 slots. Thread owns one 16B chunk of
// the node's 128B row; 8-wide predicated neighbor loop (pads gather self,
// corrected arithmetically); fp32 accumulate; hi/lo fp16 split out.
__device__ __forceinline__ void aggregate_phase(const uint4* __restrict__ X8,
                                                __half* __restrict__ xh,
                                                __half* __restrict__ xl,
                                                int n0, int n_nodes, int tid) {
    int gidx = tid >> 3;    // 0..31
    int c = tid & 7;
#pragma unroll
    for (int k = 0; k < NPB / (LTHR / GTH); k++) {
        int slot = gidx + k * (LTHR / GTH);
        int node = n0 + slot;
        float4 accA = make_float4(0.f, 0.f, 0.f, 0.f);
        float4 accB = make_float4(0.f, 0.f, 0.f, 0.f);
        if (node < n_nodes) {
            int deg = __ldg(&g_cnt[node]);
            deg = deg < ELLW ? deg : ELLW;
            const int* __restrict__ row = &g_ell[(size_t)node * ELLW];
            float4 sfA, sfB;
            cvt8(__ldg(&X8[(size_t)node * 8 + c]), sfA, sfB);
            float4 sA = make_float4(0.f, 0.f, 0.f, 0.f);
            float4 sB = make_float4(0.f, 0.f, 0.f, 0.f);
            int G = 0;
            for (int j = 0; j < deg; j += 8) {
                int4 ja = __ldg(reinterpret_cast<const int4*>(row + j));
                int4 jb = __ldg(reinterpret_cast<const int4*>(row + j + 4));
                int rem = deg - j;
                int s0 = (rem > 0) ? ja.x : node;
                int s1 = (rem > 1) ? ja.y : node;
                int s2 = (rem > 2) ? ja.z : node;
                int s3 = (rem > 3) ? ja.w : node;
                int s4 = (rem > 4) ? jb.x : node;
                int s5 = (rem > 5) ? jb.y : node;
                int s6 = (rem > 6) ? jb.z : node;
                int s7 = (rem > 7) ? jb.w : node;
                uint4 u0 = __ldg(&X8[(size_t)s0 * 8 + c]);
                uint4 u1 = __ldg(&X8[(size_t)s1 * 8 + c]);
                uint4 u2 = __ldg(&X8[(size_t)s2 * 8 + c]);
                uint4 u3 = __ldg(&X8[(size_t)s3 * 8 + c]);
                uint4 u4 = __ldg(&X8[(size_t)s4 * 8 + c]);
                uint4 u5 = __ldg(&X8[(size_t)s5 * 8 + c]);
                uint4 u6 = __ldg(&X8[(size_t)s6 * 8 + c]);
                uint4 u7 = __ldg(&X8[(size_t)s7 * 8 + c]);
                float4 a0, b0, a1, b1, a2, b2, a3, b3;
                float4 a4, b4, a5, b5, a6, b6, a7, b7;
                cvt8(u0, a0, b0); cvt8(u1, a1, b1);
                cvt8(u2, a2, b2); cvt8(u3, a3, b3);
                cvt8(u4, a4, b4); cvt8(u5, a5, b5);
                cvt8(u6, a6, b6); cvt8(u7, a7, b7);
                sA.x += (a0.x + a1.x) + (a2.x + a3.x) + (a4.x + a5.x) + (a6.x + a7.x);
                sA.y += (a0.y + a1.y) + (a2.y + a3.y) + (a4.y + a5.y) + (a6.y + a7.y);
                sA.z += (a0.z + a1.z) + (a2.z + a3.z) + (a4.z + a5.z) + (a6.z + a7.z);
                sA.w += (a0.w + a1.w) + (a2.w + a3.w) + (a4.w + a5.w) + (a6.w + a7.w);
                sB.x += (b0.x + b1.x) + (b2.x + b3.x) + (b4.x + b5.x) + (b6.x + b7.x);
                sB.y += (b0.y + b1.y) + (b2.y + b3.y) + (b4.y + b5.y) + (b6.y + b7.y);
                sB.z += (b0.z + b1.z) + (b2.z + b3.z) + (b4.z + b5.z) + (b6.z + b7.z);
                sB.w += (b0.w + b1.w) + (b2.w + b3.w) + (b4.w + b5.w) + (b6.w + b7.w);
                G += 8;
            }
            float fc = (float)(1 + deg - G);
            accA.x = fmaf(fc, sfA.x, sA.x);
            accA.y = fmaf(fc, sfA.y, sA.y);
            accA.z = fmaf(fc, sfA.z, sA.z);
            accA.w = fmaf(fc, sfA.w, sA.w);
            accB.x = fmaf(fc, sfB.x, sB.x);
            accB.y = fmaf(fc, sfB.y, sB.y);
            accB.z = fmaf(fc, sfB.z, sB.z);
            accB.w = fmaf(fc, sfB.w, sB.w);
        }
        __half2 h0 = __floats2half2_rn(accA.x, accA.y);
        __half2 h1 = __floats2half2_rn(accA.z, accA.w);
        __half2 h2 = __floats2half2_rn(accB.x, accB.y);
        __half2 h3 = __floats2half2_rn(accB.z, accB.w);
        __half2 q0 = __floats2half2_rn(accA.x - __low2float(h0), accA.y - __high2float(h0));
        __half2 q1 = __floats2half2_rn(accA.z - __low2float(h1), accA.w - __high2float(h1));
        __half2 q2 = __floats2half2_rn(accB.x - __low2float(h2), accB.y - __high2float(h2));
        __half2 q3 = __floats2half2_rn(accB.z - __low2float(h3), accB.w - __high2float(h3));
        uint4 uh, ul;
        uh.x = *reinterpret_cast<uint32_t*>(&h0);
        uh.y = *reinterpret_cast<uint32_t*>(&h1);
        uh.z = *reinterpret_cast<uint32_t*>(&h2);
        uh.w = *reinterpret_cast<uint32_t*>(&h3);
        ul.x = *reinterpret_cast<uint32_t*>(&q0);
        ul.y = *reinterpret_cast<uint32_t*>(&q1);
        ul.z = *reinterpret_cast<uint32_t*>(&q2);
        ul.w = *reinterpret_cast<uint32_t*>(&q3);
        *reinterpret_cast<uint4*>(&xh[slot * XSTR + 8 * c]) = uh;
        *reinterpret_cast<uint4*>(&xl[slot * XSTR + 8 * c]) = ul;
    }
}

// ------------------- stage W split from global into smem -------------------
__device__ __forceinline__ void stage_w(__half* __restrict__ wh,
                                        __half* __restrict__ wl,
                                        int which, int tid) {
    const uint2* gh = g_wh + which * 1024;
    const uint2* gl = g_wl + which * 1024;
    for (int idx = tid; idx < 1024; idx += LTHR) {
        int n = idx >> 4, kq = idx & 15;
        *reinterpret_cast<uint2*>(&wh[n * XSTR + kq * 4]) = __ldg(&gh[idx]);
        *reinterpret_cast<uint2*>(&wl[n * XSTR + kq * 4]) = __ldg(&gl[idx]);
    }
}

// ------ MMA: 8 warps; warp = (wrow 0-3)x16 rows, (whalf 0-1)x32 cols -------
__device__ __forceinline__ void mma_phase(const __half* __restrict__ xh,
                                          const __half* __restrict__ xl,
                                          const __half* __restrict__ wh,
                                          const __half* __restrict__ wl,
                                          int wrow, int whalf, int lane,
                                          float C[4][4]) {
    int r = lane >> 2;
    int cq = (lane & 3) * 2;
#pragma unroll
    for (int nt = 0; nt < 4; nt++) {
        C[nt][0] = 0.f; C[nt][1] = 0.f; C[nt][2] = 0.f; C[nt][3] = 0.f;
    }
    int row0 = wrow * 16 + r;
#pragma unroll
    for (int kt = 0; kt < 4; kt++) {
        int kb = kt * 16 + cq;
        uint32_t ah0 = *reinterpret_cast<const uint32_t*>(&xh[row0 * XSTR + kb]);
        uint32_t ah1 = *reinterpret_cast<const uint32_t*>(&xh[(row0 + 8) * XSTR + kb]);
        uint32_t ah2 = *reinterpret_cast<const uint32_t*>(&xh[row0 * XSTR + kb + 8]);
        uint32_t ah3 = *reinterpret_cast<const uint32_t*>(&xh[(row0 + 8) * XSTR + kb + 8]);
        uint32_t al0 = *reinterpret_cast<const uint32_t*>(&xl[row0 * XSTR + kb]);
        uint32_t al1 = *reinterpret_cast<const uint32_t*>(&xl[(row0 + 8) * XSTR + kb]);
        uint32_t al2 = *reinterpret_cast<const uint32_t*>(&xl[row0 * XSTR + kb + 8]);
        uint32_t al3 = *reinterpret_cast<const uint32_t*>(&xl[(row0 + 8) * XSTR + kb + 8]);
#pragma unroll
        for (int nt = 0; nt < 4; nt++) {
            int nrow = (whalf * 4 + nt) * 8 + r;
            uint32_t bh0 = *reinterpret_cast<const uint32_t*>(&wh[nrow * XSTR + kb]);
            uint32_t bh1 = *reinterpret_cast<const uint32_t*>(&wh[nrow * XSTR + kb + 8]);
            uint32_t bl0 = *reinterpret_cast<const uint32_t*>(&wl[nrow * XSTR + kb]);
            uint32_t bl1 = *reinterpret_cast<const uint32_t*>(&wl[nrow * XSTR + kb + 8]);
            MMA_F16(C[nt], ah0, ah1, ah2, ah3, bh0, bh1);
            MMA_F16(C[nt], ah0, ah1, ah2, ah3, bl0, bl1);
            MMA_F16(C[nt], al0, al1, al2, al3, bh0, bh1);
        }
    }
}

// ----------------- fused layer 1: agg + GEMM + relu -> fp16 h --------------
__global__ __launch_bounds__(LTHR, 4)
void fused_layer1_kernel(const float* __restrict__ B, int n_nodes) {
    __shared__ __align__(16) __half xsp[2 * NPB * XSTR];    // 18 KB
    __shared__ __align__(16) __half wsp[2 * DFEAT * XSTR];  // 18 KB
    __half* xh = xsp;
    __half* xl = xsp + NPB * XSTR;
    __half* wh = wsp;
    __half* wl = wsp + DFEAT * XSTR;

    int tid = threadIdx.x;
    int n0 = blockIdx.x * NPB;
    stage_w(wh, wl, 0, tid);
    aggregate_phase(g_x16, xh, xl, n0, n_nodes, tid);
    __syncthreads();

    int warp = tid >> 5, lane = tid & 31;
    int wrow = warp & 3, whalf = warp >> 2;
    float C[4][4];
    mma_phase(xh, xl, wh, wl, wrow, whalf, lane, C);

    int r = lane >> 2;
    int cq = (lane & 3) * 2;
    int node0 = n0 + wrow * 16 + r;
    int node1 = node0 + 8;
    uint32_t* H = reinterpret_cast<uint32_t*>(g_h16);
#pragma unroll
    for (int nt = 0; nt < 4; nt++) {
        int col = (whalf * 4 + nt) * 8 + cq;
        float2 bv = __ldg(reinterpret_cast<const float2*>(B + col));
        if (node0 < n_nodes) {
            __half2 y = __floats2half2_rn(fmaxf(C[nt][0] + bv.x, 0.f),
                                          fmaxf(C[nt][1] + bv.y, 0.f));
            H[(size_t)node0 * 32 + (col >> 1)] = *reinterpret_cast<uint32_t*>(&y);
        }
        if (node1 < n_nodes) {
            __half2 y = __floats2half2_rn(fmaxf(C[nt][2] + bv.x, 0.f),
                                          fmaxf(C[nt][3] + bv.y, 0.f));
            H[(size_t)node1 * 32 + (col >> 1)] = *reinterpret_cast<uint32_t*>(&y);
        }
    }
}

// ------------------ fused layer 2: agg + GEMM + pooling --------------------
__global__ __launch_bounds__(LTHR, 4)
void fused_layer2_kernel(const float* __restrict__ B,
                         const int* __restrict__ gid,
                         float* __restrict__ out, int n_nodes) {
    __shared__ __align__(16) __half xsp[2 * NPB * XSTR];
    __shared__ __align__(16) __half wsp[2 * DFEAT * XSTR];
    __half* xh = xsp;
    __half* xl = xsp + NPB * XSTR;
    __half* wh = wsp;
    __half* wl = wsp + DFEAT * XSTR;

    int tid = threadIdx.x;
    int n0 = blockIdx.x * NPB;
    stage_w(wh, wl, 1, tid);
    aggregate_phase(g_h16, xh, xl, n0, n_nodes, tid);
    __syncthreads();

    int warp = tid >> 5, lane = tid & 31;
    int wrow = warp & 3, whalf = warp >> 2;
    float C[4][4];
    mma_phase(xh, xl, wh, wl, wrow, whalf, lane, C);
    __syncthreads();   // xsp reads done before reuse as fp32 staging

    float* xsf = reinterpret_cast<float*>(xsp);   // 16 KB fits in 18 KB
    {
        int r = lane >> 2;
        int cq = (lane & 3) * 2;
        int row0 = wrow * 16 + r;
#pragma unroll
        for (int nt = 0; nt < 4; nt++) {
            int col = (whalf * 4 + nt) * 8 + cq;
            float2 bv = __ldg(reinterpret_cast<const float2*>(B + col));
            float2 y0, y1;
            y0.x = C[nt][0] + bv.x; y0.y = C[nt][1] + bv.y;
            y1.x = C[nt][2] + bv.x; y1.y = C[nt][3] + bv.y;
            *reinterpret_cast<float2*>(&xsf[row0 * DFEAT + col]) = y0;
            *reinterpret_cast<float2*>(&xsf[(row0 + 8) * DFEAT + col]) = y1;
        }
    }
    __syncthreads();

    // graph_id sorted: 128 threads = 2 node-halves x 64 cols.
    if (tid < 2 * DFEAT) {
        int col = tid & 63;
        int half = tid >> 6;
        int i0 = half * (NPB / 2);
        int i1 = i0 + (NPB / 2);
        int is64 = g_is64;
        float a = 0.f;
        int cur = -1;
        for (int i = i0; i < i1; i++) {
            int node = n0 + i;
            if (node >= n_nodes) break;
            int g = ld_idx(gid, node, is64);
            if (g != cur) {
                if (cur >= 0) atomicAdd(&out[(size_t)cur * DFEAT + col], a);
                cur = g;
                a = 0.f;
            }
            a += xsf[i * DFEAT + col];
        }
        if (cur >= 0) atomicAdd(&out[(size_t)cur * DFEAT + col], a);
    }
}

// ------------------------------- launcher ----------------------------------
extern "C" void kernel_launch(void* const* d_in, const int* in_sizes, int n_in,
                              void* d_out, int out_size) {
    const float* feats = (const float*)d_in[0];
    const int*   src   = (const int*)d_in[1];
    const int*   dst   = (const int*)d_in[2];
    const int*   gid   = (const int*)d_in[3];
    const float* W1    = (const float*)d_in[4];
    const float* b1    = (const float*)d_in[5];
    const float* W2    = (const float*)d_in[6];
    const float* b2    = (const float*)d_in[7];
    float* out = (float*)d_out;

    int n_nodes = in_sizes[0] / DFEAT;
    int n_edges = in_sizes[1];
    int n8 = n_nodes * 8;

    int sgrid = (n8 + 255) / 256;   // covers n_nodes, out_size, 2048, n8
    int egrid = (n_edges + 255) / 256;
    int lgrid = (n_nodes + NPB - 1) / NPB;

    setup_kernel<<<sgrid, 256>>>(reinterpret_cast<const float4*>(feats),
                                 W1, W2, src, out, n_nodes, out_size, n8);
    fill_kernel<<<egrid, 256>>>(src, dst, n_edges);
    fused_layer1_kernel<<<lgrid, LTHR>>>(b1, n_nodes);
    fused_layer2_kernel<<<lgrid, LTHR>>>(b2, gid, out, n_nodes);
}

// round 14
// speedup vs baseline: 1.5005x; 1.0217x over previous
#include <cuda_runtime.h>
#include <cuda_fp16.h>
#include <cstdint>

// ---------------------------------------------------------------------------
// GIN, fused layers with fp16 gather operands + self-padded ELL rows:
//   setup: zero cnt/out + int64-detect + W split + feats->fp16 (ONE kernel)
//   fill:  ELL adjacency;  pad: slots [deg, ceil8(deg)) <- self index
//   fused1: unconditional fp16 gather + HADD2 pair-reduce + split fp16 MMA
//   fused2: same + bias + sorted-gid pooling
// GEMM: x@W ~= xh@Wh + xh@Wl + xl@Wh (fp16 operands, fp32 accum).
// Self-pads corrected arithmetically: acc = sum + (1 + deg - 8*iters)*self.
// ---------------------------------------------------------------------------

#define DFEAT 64
#define NPB   64
#define LTHR  256
#define GTH   8        // threads per node in gather (16B chunk each)
#define XSTR  72       // fp16 row stride in smem (144B)
#define ELLW  96
#define MAX_NODES 100032

__device__ uint4 g_x16[(size_t)MAX_NODES * 8];   // fp16 feats rows (128B)
__device__ uint4 g_h16[(size_t)MAX_NODES * 8];   // fp16 h rows
__device__ uint2 g_wh[2 * 1024];                 // W hi fp16 [which][n*16+kq]
__device__ uint2 g_wl[2 * 1024];                 // W lo fp16
__device__ int   g_ell[(size_t)MAX_NODES * ELLW];
__device__ int   g_cnt[MAX_NODES];
__device__ int   g_is64;

__device__ __forceinline__ int ld_idx(const int* __restrict__ p, int i, int is64) {
    return is64 ? p[2 * i] : p[i];
}

#define MMA_F16(C, a0, a1, a2, a3, b0, b1)                                    \
    asm volatile(                                                             \
        "mma.sync.aligned.m16n8k16.row.col.f32.f16.f16.f32 "                  \
        "{%0,%1,%2,%3}, {%4,%5,%6,%7}, {%8,%9}, {%0,%1,%2,%3};"               \
        : "+f"((C)[0]), "+f"((C)[1]), "+f"((C)[2]), "+f"((C)[3])              \
        : "r"(a0), "r"(a1), "r"(a2), "r"(a3), "r"(b0), "r"(b1))

// uint4 (8 fp16) -> two float4
__device__ __forceinline__ void cvt8(uint4 u, float4& A, float4& B) {
    __half2 h0 = *reinterpret_cast<__half2*>(&u.x);
    __half2 h1 = *reinterpret_cast<__half2*>(&u.y);
    __half2 h2 = *reinterpret_cast<__half2*>(&u.z);
    __half2 h3 = *reinterpret_cast<__half2*>(&u.w);
    float2 f0 = __half22float2(h0);
    float2 f1 = __half22float2(h1);
    float2 f2 = __half22float2(h2);
    float2 f3 = __half22float2(h3);
    A = make_float4(f0.x, f0.y, f1.x, f1.y);
    B = make_float4(f2.x, f2.y, f3.x, f3.y);
}

// packed fp16x2 add across a uint4 (4 HADD2)
__device__ __forceinline__ uint4 hadd4(uint4 a, uint4 b) {
    uint4 r;
    __half2* pa = reinterpret_cast<__half2*>(&a);
    __half2* pb = reinterpret_cast<__half2*>(&b);
    __half2* pr = reinterpret_cast<__half2*>(&r);
    pr[0] = __hadd2(pa[0], pb[0]);
    pr[1] = __hadd2(pa[1], pb[1]);
    pr[2] = __hadd2(pa[2], pb[2]);
    pr[3] = __hadd2(pa[3], pb[3]);
    return r;
}

// ---------------- setup: zero + detect + W split + feats->fp16 -------------
__global__ void setup_kernel(const float4* __restrict__ X4,
                             const float* __restrict__ W1,
                             const float* __restrict__ W2,
                             const int* __restrict__ srcw,
                             float* __restrict__ out,
                             int n_nodes, int out_n, int n8) {
    int i = blockIdx.x * blockDim.x + threadIdx.x;
    if (i < n_nodes) g_cnt[i] = 0;
    if (i < out_n) out[i] = 0.f;
    if (blockIdx.x == 0 && threadIdx.x < 32) {
        int v = srcw[2 * threadIdx.x + 1];
        unsigned ok = __ballot_sync(0xFFFFFFFFu, v == 0);
        if (threadIdx.x == 0) g_is64 = (ok == 0xFFFFFFFFu) ? 1 : 0;
    }
    if (i < 2048) {   // W split: fp32 [k][n] -> fp16 hi/lo [n][k]
        int which = i >> 10;
        int r = i & 1023;
        int n = r >> 4, kq = r & 15;
        const float* W = which ? W2 : W1;
        float w0 = __ldg(&W[(kq * 4 + 0) * DFEAT + n]);
        float w1 = __ldg(&W[(kq * 4 + 1) * DFEAT + n]);
        float w2 = __ldg(&W[(kq * 4 + 2) * DFEAT + n]);
        float w3 = __ldg(&W[(kq * 4 + 3) * DFEAT + n]);
        __half2 h01 = __floats2half2_rn(w0, w1);
        __half2 h23 = __floats2half2_rn(w2, w3);
        __half2 l01 = __floats2half2_rn(w0 - __low2float(h01), w1 - __high2float(h01));
        __half2 l23 = __floats2half2_rn(w2 - __low2float(h23), w3 - __high2float(h23));
        uint2 uh, ul;
        uh.x = *reinterpret_cast<uint32_t*>(&h01);
        uh.y = *reinterpret_cast<uint32_t*>(&h23);
        ul.x = *reinterpret_cast<uint32_t*>(&l01);
        ul.y = *reinterpret_cast<uint32_t*>(&l23);
        g_wh[i] = uh;
        g_wl[i] = ul;
    }
    if (i < n8) {     // feats fp32 -> fp16 (8 values per thread)
        float4 a = __ldg(&X4[2 * i]);
        float4 b = __ldg(&X4[2 * i + 1]);
        __half2 h0 = __floats2half2_rn(a.x, a.y);
        __half2 h1 = __floats2half2_rn(a.z, a.w);
        __half2 h2 = __floats2half2_rn(b.x, b.y);
        __half2 h3 = __floats2half2_rn(b.z, b.w);
        uint4 u;
        u.x = *reinterpret_cast<uint32_t*>(&h0);
        u.y = *reinterpret_cast<uint32_t*>(&h1);
        u.z = *reinterpret_cast<uint32_t*>(&h2);
        u.w = *reinterpret_cast<uint32_t*>(&h3);
        g_x16[i] = u;
    }
}

// ------------------------------- ELL fill ----------------------------------
__global__ void fill_kernel(const int* __restrict__ src,
                            const int* __restrict__ dst, int n_edges) {
    int e = blockIdx.x * blockDim.x + threadIdx.x;
    if (e >= n_edges) return;
    int is64 = g_is64;
    int d = ld_idx(dst, e, is64);
    int s = ld_idx(src, e, is64);
    int pos = atomicAdd(&g_cnt[d], 1);
    if (pos < ELLW) g_ell[(size_t)d * ELLW + pos] = s;
}

// ------------- pad: ELL slots [deg, ceil8(deg)) <- self index --------------
__global__ void pad_kernel(int n_nodes) {
    int t = blockIdx.x * blockDim.x + threadIdx.x;
    int node = t >> 3;
    if (node >= n_nodes) return;
    int q = t & 7;
    int deg = g_cnt[node];
    deg = deg < ELLW ? deg : ELLW;
    int padded = (deg + 7) & ~7;
    padded = padded < ELLW ? padded : ELLW;
    int idx = deg + q;
    if (idx < padded) g_ell[(size_t)node * ELLW + idx] = node;
}

// ---------- aggregate: unconditional fp16 gather, HADD2 pair-reduce --------
// 32 groups of 8 threads; group handles 2 slots. Thread owns one 16B chunk of
// the node's 128B row. Rows are self-padded to a multiple of 8, so the loop
// gathers blindly; self-pad over-count corrected via fc = 1 + deg - 8*iters.
__device__ __forceinline__ void aggregate_phase(const uint4* __restrict__ X8,
                                                __half* __restrict__ xh,
                                                __half* __restrict__ xl,
                                                int n0, int n_nodes, int tid) {
    int gidx = tid >> 3;    // 0..31
    int c = tid & 7;
#pragma unroll
    for (int k = 0; k < NPB / (LTHR / GTH); k++) {
        int slot = gidx + k * (LTHR / GTH);
        int node = n0 + slot;
        float4 accA = make_float4(0.f, 0.f, 0.f, 0.f);
        float4 accB = make_float4(0.f, 0.f, 0.f, 0.f);
        if (node < n_nodes) {
            int deg = __ldg(&g_cnt[node]);
            deg = deg < ELLW ? deg : ELLW;
            const int* __restrict__ row = &g_ell[(size_t)node * ELLW];
            float4 sfA, sfB;
            cvt8(__ldg(&X8[(size_t)node * 8 + c]), sfA, sfB);
            float4 sA = make_float4(0.f, 0.f, 0.f, 0.f);
            float4 sB = make_float4(0.f, 0.f, 0.f, 0.f);
            int G = 0;
            for (int j = 0; j < deg; j += 8) {
                int4 ja = __ldg(reinterpret_cast<const int4*>(row + j));
                int4 jb = __ldg(reinterpret_cast<const int4*>(row + j + 4));
                uint4 u0 = __ldg(&X8[(size_t)ja.x * 8 + c]);
                uint4 u1 = __ldg(&X8[(size_t)ja.y * 8 + c]);
                uint4 u2 = __ldg(&X8[(size_t)ja.z * 8 + c]);
                uint4 u3 = __ldg(&X8[(size_t)ja.w * 8 + c]);
                uint4 u4 = __ldg(&X8[(size_t)jb.x * 8 + c]);
                uint4 u5 = __ldg(&X8[(size_t)jb.y * 8 + c]);
                uint4 u6 = __ldg(&X8[(size_t)jb.z * 8 + c]);
                uint4 u7 = __ldg(&X8[(size_t)jb.w * 8 + c]);
                // one fp16 pair-add level (8 -> 4), then fp32 accumulate
                uint4 p0 = hadd4(u0, u1);
                uint4 p1 = hadd4(u2, u3);
                uint4 p2 = hadd4(u4, u5);
                uint4 p3 = hadd4(u6, u7);
                float4 a0, b0, a1, b1, a2, b2, a3, b3;
                cvt8(p0, a0, b0); cvt8(p1, a1, b1);
                cvt8(p2, a2, b2); cvt8(p3, a3, b3);
                sA.x += (a0.x + a1.x) + (a2.x + a3.x);
                sA.y += (a0.y + a1.y) + (a2.y + a3.y);
                sA.z += (a0.z + a1.z) + (a2.z + a3.z);
                sA.w += (a0.w + a1.w) + (a2.w + a3.w);
                sB.x += (b0.x + b1.x) + (b2.x + b3.x);
                sB.y += (b0.y + b1.y) + (b2.y + b3.y);
                sB.z += (b0.z + b1.z) + (b2.z + b3.z);
                sB.w += (b0.w + b1.w) + (b2.w + b3.w);
                G += 8;
            }
            float fc = (float)(1 + deg - G);
            accA.x = fmaf(fc, sfA.x, sA.x);
            accA.y = fmaf(fc, sfA.y, sA.y);
            accA.z = fmaf(fc, sfA.z, sA.z);
            accA.w = fmaf(fc, sfA.w, sA.w);
            accB.x = fmaf(fc, sfB.x, sB.x);
            accB.y = fmaf(fc, sfB.y, sB.y);
            accB.z = fmaf(fc, sfB.z, sB.z);
            accB.w = fmaf(fc, sfB.w, sB.w);
        }
        __half2 h0 = __floats2half2_rn(accA.x, accA.y);
        __half2 h1 = __floats2half2_rn(accA.z, accA.w);
        __half2 h2 = __floats2half2_rn(accB.x, accB.y);
        __half2 h3 = __floats2half2_rn(accB.z, accB.w);
        __half2 q0 = __floats2half2_rn(accA.x - __low2float(h0), accA.y - __high2float(h0));
        __half2 q1 = __floats2half2_rn(accA.z - __low2float(h1), accA.w - __high2float(h1));
        __half2 q2 = __floats2half2_rn(accB.x - __low2float(h2), accB.y - __high2float(h2));
        __half2 q3 = __floats2half2_rn(accB.z - __low2float(h3), accB.w - __high2float(h3));
        uint4 uh, ul;
        uh.x = *reinterpret_cast<uint32_t*>(&h0);
        uh.y = *reinterpret_cast<uint32_t*>(&h1);
        uh.z = *reinterpret_cast<uint32_t*>(&h2);
        uh.w = *reinterpret_cast<uint32_t*>(&h3);
        ul.x = *reinterpret_cast<uint32_t*>(&q0);
        ul.y = *reinterpret_cast<uint32_t*>(&q1);
        ul.z = *reinterpret_cast<uint32_t*>(&q2);
        ul.w = *reinterpret_cast<uint32_t*>(&q3);
        *reinterpret_cast<uint4*>(&xh[slot * XSTR + 8 * c]) = uh;
        *reinterpret_cast<uint4*>(&xl[slot * XSTR + 8 * c]) = ul;
    }
}

// ------------------- stage W split from global into smem -------------------
__device__ __forceinline__ void stage_w(__half* __restrict__ wh,
                                        __half* __restrict__ wl,
                                        int which, int tid) {
    const uint2* gh = g_wh + which * 1024;
    const uint2* gl = g_wl + which * 1024;
    for (int idx = tid; idx < 1024; idx += LTHR) {
        int n = idx >> 4, kq = idx & 15;
        *reinterpret_cast<uint2*>(&wh[n * XSTR + kq * 4]) = __ldg(&gh[idx]);
        *reinterpret_cast<uint2*>(&wl[n * XSTR + kq * 4]) = __ldg(&gl[idx]);
    }
}

// ------ MMA: 8 warps; warp = (wrow 0-3)x16 rows, (whalf 0-1)x32 cols -------
__device__ __forceinline__ void mma_phase(const __half* __restrict__ xh,
                                          const __half* __restrict__ xl,
                                          const __half* __restrict__ wh,
                                          const __half* __restrict__ wl,
                                          int wrow, int whalf, int lane,
                                          float C[4][4]) {
    int r = lane >> 2;
    int cq = (lane & 3) * 2;
#pragma unroll
    for (int nt = 0; nt < 4; nt++) {
        C[nt][0] = 0.f; C[nt][1] = 0.f; C[nt][2] = 0.f; C[nt][3] = 0.f;
    }
    int row0 = wrow * 16 + r;
#pragma unroll
    for (int kt = 0; kt < 4; kt++) {
        int kb = kt * 16 + cq;
        uint32_t ah0 = *reinterpret_cast<const uint32_t*>(&xh[row0 * XSTR + kb]);
        uint32_t ah1 = *reinterpret_cast<const uint32_t*>(&xh[(row0 + 8) * XSTR + kb]);
        uint32_t ah2 = *reinterpret_cast<const uint32_t*>(&xh[row0 * XSTR + kb + 8]);
        uint32_t ah3 = *reinterpret_cast<const uint32_t*>(&xh[(row0 + 8) * XSTR + kb + 8]);
        uint32_t al0 = *reinterpret_cast<const uint32_t*>(&xl[row0 * XSTR + kb]);
        uint32_t al1 = *reinterpret_cast<const uint32_t*>(&xl[(row0 + 8) * XSTR + kb]);
        uint32_t al2 = *reinterpret_cast<const uint32_t*>(&xl[row0 * XSTR + kb + 8]);
        uint32_t al3 = *reinterpret_cast<const uint32_t*>(&xl[(row0 + 8) * XSTR + kb + 8]);
#pragma unroll
        for (int nt = 0; nt < 4; nt++) {
            int nrow = (whalf * 4 + nt) * 8 + r;
            uint32_t bh0 = *reinterpret_cast<const uint32_t*>(&wh[nrow * XSTR + kb]);
            uint32_t bh1 = *reinterpret_cast<const uint32_t*>(&wh[nrow * XSTR + kb + 8]);
            uint32_t bl0 = *reinterpret_cast<const uint32_t*>(&wl[nrow * XSTR + kb]);
            uint32_t bl1 = *reinterpret_cast<const uint32_t*>(&wl[nrow * XSTR + kb + 8]);
            MMA_F16(C[nt], ah0, ah1, ah2, ah3, bh0, bh1);
            MMA_F16(C[nt], ah0, ah1, ah2, ah3, bl0, bl1);
            MMA_F16(C[nt], al0, al1, al2, al3, bh0, bh1);
        }
    }
}

// ----------------- fused layer 1: agg + GEMM + relu -> fp16 h --------------
__global__ __launch_bounds__(LTHR, 4)
void fused_layer1_kernel(const float* __restrict__ B, int n_nodes) {
    __shared__ __align__(16) __half xsp[2 * NPB * XSTR];    // 18 KB
    __shared__ __align__(16) __half wsp[2 * DFEAT * XSTR];  // 18 KB
    __half* xh = xsp;
    __half* xl = xsp + NPB * XSTR;
    __half* wh = wsp;
    __half* wl = wsp + DFEAT * XSTR;

    int tid = threadIdx.x;
    int n0 = blockIdx.x * NPB;
    stage_w(wh, wl, 0, tid);
    aggregate_phase(g_x16, xh, xl, n0, n_nodes, tid);
    __syncthreads();

    int warp = tid >> 5, lane = tid & 31;
    int wrow = warp & 3, whalf = warp >> 2;
    float C[4][4];
    mma_phase(xh, xl, wh, wl, wrow, whalf, lane, C);

    int r = lane >> 2;
    int cq = (lane & 3) * 2;
    int node0 = n0 + wrow * 16 + r;
    int node1 = node0 + 8;
    uint32_t* H = reinterpret_cast<uint32_t*>(g_h16);
#pragma unroll
    for (int nt = 0; nt < 4; nt++) {
        int col = (whalf * 4 + nt) * 8 + cq;
        float2 bv = __ldg(reinterpret_cast<const float2*>(B + col));
        if (node0 < n_nodes) {
            __half2 y = __floats2half2_rn(fmaxf(C[nt][0] + bv.x, 0.f),
                                          fmaxf(C[nt][1] + bv.y, 0.f));
            H[(size_t)node0 * 32 + (col >> 1)] = *reinterpret_cast<uint32_t*>(&y);
        }
        if (node1 < n_nodes) {
            __half2 y = __floats2half2_rn(fmaxf(C[nt][2] + bv.x, 0.f),
                                          fmaxf(C[nt][3] + bv.y, 0.f));
            H[(size_t)node1 * 32 + (col >> 1)] = *reinterpret_cast<uint32_t*>(&y);
        }
    }
}

// ------------------ fused layer 2: agg + GEMM + pooling --------------------
__global__ __launch_bounds__(LTHR, 4)
void fused_layer2_kernel(const float* __restrict__ B,
                         const int* __restrict__ gid,
                         float* __restrict__ out, int n_nodes) {
    __shared__ __align__(16) __half xsp[2 * NPB * XSTR];
    __shared__ __align__(16) __half wsp[2 * DFEAT * XSTR];
    __half* xh = xsp;
    __half* xl = xsp + NPB * XSTR;
    __half* wh = wsp;
    __half* wl = wsp + DFEAT * XSTR;

    int tid = threadIdx.x;
    int n0 = blockIdx.x * NPB;
    stage_w(wh, wl, 1, tid);
    aggregate_phase(g_h16, xh, xl, n0, n_nodes, tid);
    __syncthreads();

    int warp = tid >> 5, lane = tid & 31;
    int wrow = warp & 3, whalf = warp >> 2;
    float C[4][4];
    mma_phase(xh, xl, wh, wl, wrow, whalf, lane, C);
    __syncthreads();   // xsp reads done before reuse as fp32 staging

    float* xsf = reinterpret_cast<float*>(xsp);   // 16 KB fits in 18 KB
    {
        int r = lane >> 2;
        int cq = (lane & 3) * 2;
        int row0 = wrow * 16 + r;
#pragma unroll
        for (int nt = 0; nt < 4; nt++) {
            int col = (whalf * 4 + nt) * 8 + cq;
            float2 bv = __ldg(reinterpret_cast<const float2*>(B + col));
            float2 y0, y1;
            y0.x = C[nt][0] + bv.x; y0.y = C[nt][1] + bv.y;
            y1.x = C[nt][2] + bv.x; y1.y = C[nt][3] + bv.y;
            *reinterpret_cast<float2*>(&xsf[row0 * DFEAT + col]) = y0;
            *reinterpret_cast<float2*>(&xsf[(row0 + 8) * DFEAT + col]) = y1;
        }
    }
    __syncthreads();

    // graph_id sorted: 128 threads = 2 node-halves x 64 cols.
    if (tid < 2 * DFEAT) {
        int col = tid & 63;
        int half = tid >> 6;
        int i0 = half * (NPB / 2);
        int i1 = i0 + (NPB / 2);
        int is64 = g_is64;
        float a = 0.f;
        int cur = -1;
        for (int i = i0; i < i1; i++) {
            int node = n0 + i;
            if (node >= n_nodes) break;
            int g = ld_idx(gid, node, is64);
            if (g != cur) {
                if (cur >= 0) atomicAdd(&out[(size_t)cur * DFEAT + col], a);
                cur = g;
                a = 0.f;
            }
            a += xsf[i * DFEAT + col];
        }
        if (cur >= 0) atomicAdd(&out[(size_t)cur * DFEAT + col], a);
    }
}

// ------------------------------- launcher ----------------------------------
extern "C" void kernel_launch(void* const* d_in, const int* in_sizes, int n_in,
                              void* d_out, int out_size) {
    const float* feats = (const float*)d_in[0];
    const int*   src   = (const int*)d_in[1];
    const int*   dst   = (const int*)d_in[2];
    const int*   gid   = (const int*)d_in[3];
    const float* W1    = (const float*)d_in[4];
    const float* b1    = (const float*)d_in[5];
    const float* W2    = (const float*)d_in[6];
    const float* b2    = (const float*)d_in[7];
    float* out = (float*)d_out;

    int n_nodes = in_sizes[0] / DFEAT;
    int n_edges = in_sizes[1];
    int n8 = n_nodes * 8;

    int sgrid = (n8 + 255) / 256;   // covers n_nodes, out_size, 2048, n8
    int egrid = (n_edges + 255) / 256;
    int pgrid = (n8 + 255) / 256;
    int lgrid = (n_nodes + NPB - 1) / NPB;

    setup_kernel<<<sgrid, 256>>>(reinterpret_cast<const float4*>(feats),
                                 W1, W2, src, out, n_nodes, out_size, n8);
    fill_kernel<<<egrid, 256>>>(src, dst, n_edges);
    pad_kernel<<<pgrid, 256>>>(n_nodes);
    fused_layer1_kernel<<<lgrid, LTHR>>>(b1, n_nodes);
    fused_layer2_kernel<<<lgrid, LTHR>>>(b2, gid, out, n_nodes);
}